// round 13
// baseline (speedup 1.0000x reference)
#include <cuda_runtime.h>
#include <cuda_bf16.h>
#include <cstdint>

// S4D via mma.sync bf16 (3x split), R13:
//  Phase-1 transcendental elimination: ONE expf + ONE sincosf per thread
//  (w = exp(dt*A)); all slice starts built algebraically:
//    w^8 by 3 squarings, w^{8s} by segmented shfl prefix-product (width 16),
//    Q start w^{256 s} = (w^{8s})^32 by 5 squarings, wC=w^128 by 4 squarings.
//  Layout n = tid>>4, s = tid&15 so a mode's 16 slices share a shfl segment.
//
// Per h:  K[m + 128c] = sum_k QT[c,k] * PT[m,k]
//   PT[m,2n] = Re(2*Ck_n*w_n^m),  PT[m,2n+1] = Im(...)
//   QT[c,2n] = Re((w_n^128)^c),   QT[c,2n+1] = -Im(...)
// GEMM M=32(c) x N=128(m) x K=64, mma.m16n8k16.row.col, fp32 acc.
// Tiles k-major, 128B rows, 16B-chunk swizzle: chunk ^= (row & 7).

typedef uint32_t u32;

#define PPLANE 16384   // bytes per P plane (128 x 64 bf16)
#define QPLANE  4096   // bytes per Q plane ( 32 x 64 bf16)

__device__ __forceinline__ u32 smem_u32(const void* p) {
    u32 a;
    asm("{ .reg .u64 t; cvta.to.shared.u64 t, %1; cvt.u32.u64 %0, t; }"
        : "=r"(a) : "l"(p));
    return a;
}

__device__ __forceinline__ void ldsm4(u32 addr, u32* r) {
    asm volatile("ldmatrix.sync.aligned.m8n8.x4.shared.b16 {%0,%1,%2,%3}, [%4];"
                 : "=r"(r[0]), "=r"(r[1]), "=r"(r[2]), "=r"(r[3]) : "r"(addr));
}

__device__ __forceinline__ void mma_bf16(float* d, const u32* a, u32 b0, u32 b1) {
    asm volatile(
        "mma.sync.aligned.m16n8k16.row.col.f32.bf16.bf16.f32 "
        "{%0,%1,%2,%3}, {%4,%5,%6,%7}, {%8,%9}, {%0,%1,%2,%3};"
        : "+f"(d[0]), "+f"(d[1]), "+f"(d[2]), "+f"(d[3])
        : "r"(a[0]), "r"(a[1]), "r"(a[2]), "r"(a[3]), "r"(b0), "r"(b1));
}

__device__ __forceinline__ void cmul(float& xr, float& xi, float yr, float yi) {
    const float t = xr * yr - xi * yi;
    xi = xr * yi + xi * yr;
    xr = t;
}

// hi/lo bf16 split store: hi at base+off, lo at base+off+plane
__device__ __forceinline__ void split_store(char* base, u32 off, int plane,
                                            float x, float y) {
    __nv_bfloat162 h = __float22bfloat162_rn(make_float2(x, y));
    float xl = x - __bfloat162float(h.x);
    float yl = y - __bfloat162float(h.y);
    __nv_bfloat162 l = __float22bfloat162_rn(make_float2(xl, yl));
    *reinterpret_cast<__nv_bfloat162*>(base + off)         = h;
    *reinterpret_cast<__nv_bfloat162*>(base + off + plane) = l;
}

__global__ __launch_bounds__(512, 3)
void s4d_kernel(const float* __restrict__ log_dt,
                const float* __restrict__ C,
                const float* __restrict__ log_A_real,
                const float* __restrict__ A_imag,
                float* __restrict__ out)
{
    __shared__ __align__(128) __nv_bfloat16 sP[2][128 * 64];  // hi, lo  32 KB
    __shared__ __align__(128) __nv_bfloat16 sQ[2][ 32 * 64];  // hi, lo   8 KB

    const int h    = blockIdx.x;
    const int tid  = threadIdx.x;
    const int lane = tid & 31;
    const int wrp  = tid >> 5;   // 0..15

    // ================= Phase 1: build swizzled bf16 hi/lo tiles ============
    {
        const int n = tid >> 4;          // mode (shfl-segment uniform)
        const int s = tid & 15;          // slice 0..15

        const float dt = expf(log_dt[h]);
        const float Ar = -expf(log_A_real[h * 32 + n]);
        const float Ai = A_imag[h * 32 + n];
        const float dr = dt * Ar, di = dt * Ai;

        // --- the ONLY transcendentals: w = exp(dt*A) ---
        float sn, cs;
        const float er = expf(dr);
        sincosf(di, &sn, &cs);
        const float wr = er * cs, wi = er * sn;

        // P0 = 2*C*(w-1)/A
        const float inv = 1.0f / (Ar * Ar + Ai * Ai);
        const float nr = wr - 1.0f, ni = wi;
        const float gr = (nr * Ar + ni * Ai) * inv;
        const float gi = (ni * Ar - nr * Ai) * inv;
        const float Cr = C[(h * 32 + n) * 2 + 0];
        const float Ci = C[(h * 32 + n) * 2 + 1];
        const float p0r = 2.0f * (Cr * gr - Ci * gi);
        const float p0i = 2.0f * (Cr * gi + Ci * gr);

        // w^8 by 3 squarings
        float w8r = wr, w8i = wi;
        cmul(w8r, w8i, w8r, w8i);          // w^2
        cmul(w8r, w8i, w8r, w8i);          // w^4
        cmul(w8r, w8i, w8r, w8i);          // w^8

        // x = w^{8s} via segmented (width 16) shfl prefix product
        float xr = (s == 0) ? 1.0f : w8r;
        float xi = (s == 0) ? 0.0f : w8i;
        #pragma unroll
        for (int d = 1; d < 16; d <<= 1) {
            const float yr = __shfl_up_sync(0xffffffffu, xr, d, 16);
            const float yi = __shfl_up_sync(0xffffffffu, xi, d, 16);
            if (s >= d) cmul(xr, xi, yr, yi);
        }

        // wC = w^128 from w^8 by 4 squarings
        float wCr = w8r, wCi = w8i;
        cmul(wCr, wCi, wCr, wCi);          // w^16
        cmul(wCr, wCi, wCr, wCi);          // w^32
        cmul(wCr, wCi, wCr, wCi);          // w^64
        cmul(wCr, wCi, wCr, wCi);          // w^128

        // Q start = wC^{2s} = (w^{8s})^32 by 5 squarings
        float qr = xr, qi = xi;
        cmul(qr, qi, qr, qi);
        cmul(qr, qi, qr, qi);
        cmul(qr, qi, qr, qi);
        cmul(qr, qi, qr, qi);
        cmul(qr, qi, qr, qi);              // x^32

        const u32 kb   = 4u * (u32)n;
        const u32 colb = ((u32)(n >> 2) << 4) | (kb & 15u);

        // ---- PT rows m in [8s, 8s+8): p = P0 * w^{8s}, step by w ----
        {
            float pr = p0r, pi = p0i;
            cmul(pr, pi, xr, xi);

            char* Pc = (char*)sP;
            const u32 pbase = (u32)(8 * s) * 128u + colb;
            #pragma unroll
            for (int k = 0; k < 8; k++) {
                const u32 off = (pbase ^ (((u32)k) << 4)) + (u32)k * 128u;
                split_store(Pc, off, PPLANE, pr, pi);
                cmul(pr, pi, wr, wi);
            }
        }

        // ---- QT rows c in [2s, 2s+2): q, then q*wC ----
        {
            char* Qc = (char*)sQ;
            const u32 qbase = (u32)(2 * s) * 128u + colb;
            const u32 xq    = 2u * (u32)(s & 3);
            #pragma unroll
            for (int k = 0; k < 2; k++) {
                const u32 off = (qbase ^ ((xq + (u32)k) << 4)) + (u32)k * 128u;
                split_store(Qc, off, QPLANE, qr, -qi);
                cmul(qr, qi, wCr, wCi);
            }
        }
    }
    __syncthreads();

    // ================= Phase 2: ldmatrix + mma.sync ========================
    // 16 warps: c-half r0 = 16*(wrp&1), m j-pair jp = wrp>>1 (j = 2jp, 2jp+1)
    const int gid = lane >> 2;
    const int tig = lane & 3;
    const int r0  = 16 * (wrp & 1);
    const int jp  = wrp >> 1;

    u32 aaddr[4], baddr[4];
    {
        const u32 Qb = smem_u32(sQ);
        const u32 Pb = smem_u32(sP);
        // A: row = r0 + (lane&15), k-half = lane>>4
        {
            const u32 row = (u32)(r0 + (lane & 15));
            const u32 hh  = (u32)(lane >> 4);
            const u32 rt  = Qb + row * 128u;
            const u32 x   = row & 7u;
            #pragma unroll
            for (int kc = 0; kc < 4; kc++)
                aaddr[kc] = rt + ((((2u * kc + hh) ^ x)) << 4);
        }
        // B: row = 8*(2jp + (lane>>4)) + (lane&7); k-half = (lane>>3)&1
        {
            const u32 row = 8u * (u32)(2 * jp + (lane >> 4)) + (lane & 7u);
            const u32 hb  = (u32)((lane >> 3) & 1);
            const u32 rt  = Pb + row * 128u;
            const u32 x   = row & 7u;
            #pragma unroll
            for (int kc = 0; kc < 4; kc++)
                baddr[kc] = rt + ((((2u * kc + hb) ^ x)) << 4);
        }
    }

    float acc[2][4];
    #pragma unroll
    for (int j = 0; j < 2; j++)
        #pragma unroll
        for (int r = 0; r < 4; r++) acc[j][r] = 0.0f;

    #pragma unroll
    for (int kc = 0; kc < 4; kc++) {
        u32 ahi[4], alo[4], bh[4], bl[4];
        ldsm4(aaddr[kc],          ahi);
        ldsm4(aaddr[kc] + QPLANE, alo);
        ldsm4(baddr[kc],          bh);
        ldsm4(baddr[kc] + PPLANE, bl);

        #pragma unroll
        for (int jj = 0; jj < 2; jj++) {
            const int o = jj * 2;
            mma_bf16(acc[jj], ahi, bh[o], bh[o + 1]);   // hi*hi
            mma_bf16(acc[jj], ahi, bl[o], bl[o + 1]);   // hi*lo
            mma_bf16(acc[jj], alo, bh[o], bh[o + 1]);   // lo*hi
        }
    }

    // ---- store D fragments: c = r0+gid (+8), m = 8*(2jp+jj) + 2*tig ----
    float* o = out + (size_t)h * 4096;
    #pragma unroll
    for (int jj = 0; jj < 2; jj++) {
        const int m = 8 * (2 * jp + jj) + 2 * tig;
        const int c = r0 + gid;
        *reinterpret_cast<float2*>(o + c * 128 + m) =
            make_float2(acc[jj][0], acc[jj][1]);
        *reinterpret_cast<float2*>(o + (c + 8) * 128 + m) =
            make_float2(acc[jj][2], acc[jj][3]);
    }
}

extern "C" void kernel_launch(void* const* d_in, const int* in_sizes, int n_in,
                              void* d_out, int out_size)
{
    const float* log_dt     = (const float*)d_in[0];
    const float* C          = (const float*)d_in[1];
    const float* log_A_real = (const float*)d_in[2];
    const float* A_imag     = (const float*)d_in[3];
    float*       out        = (float*)d_out;

    const int H = in_sizes[0];   // 1024
    s4d_kernel<<<H, 512>>>(log_dt, C, log_A_real, A_imag, out);
}

// round 14
// speedup vs baseline: 2.8942x; 2.8942x over previous
#include <cuda_runtime.h>
#include <cuda_bf16.h>
#include <cstdint>

// S4D via mma.sync bf16 (3x split), R14:
//  R12's bank-friendly layout (n = tid&31 -> stores span all 32 banks)
//  + transcendental elimination WITHOUT the R13 shfl lane-remap (which
//  made P-store strides 1024B and caused 16-way bank conflicts).
//  Per thread: 3 expf + 1 sincosf (dt, Ar, w); slice starts by binary
//  powering: w^{8s} = prod over bits of s of {w8,w16,w32,w64};
//  wC = w128 = w64^2; Q start = (w^{8s})^32 by 5 squarings.
//
// Per h:  K[m + 128c] = sum_k QT[c,k] * PT[m,k]
//   PT[m,2n] = Re(2*Ck_n*w_n^m),  PT[m,2n+1] = Im(...)
//   QT[c,2n] = Re((w_n^128)^c),   QT[c,2n+1] = -Im(...)
// GEMM M=32(c) x N=128(m) x K=64, mma.m16n8k16.row.col, fp32 acc.
// Tiles k-major, 128B rows, 16B-chunk swizzle: chunk ^= (row & 7).

typedef uint32_t u32;

#define PPLANE 16384   // bytes per P plane (128 x 64 bf16)
#define QPLANE  4096   // bytes per Q plane ( 32 x 64 bf16)

__device__ __forceinline__ u32 smem_u32(const void* p) {
    u32 a;
    asm("{ .reg .u64 t; cvta.to.shared.u64 t, %1; cvt.u32.u64 %0, t; }"
        : "=r"(a) : "l"(p));
    return a;
}

__device__ __forceinline__ void ldsm4(u32 addr, u32* r) {
    asm volatile("ldmatrix.sync.aligned.m8n8.x4.shared.b16 {%0,%1,%2,%3}, [%4];"
                 : "=r"(r[0]), "=r"(r[1]), "=r"(r[2]), "=r"(r[3]) : "r"(addr));
}

__device__ __forceinline__ void mma_bf16(float* d, const u32* a, u32 b0, u32 b1) {
    asm volatile(
        "mma.sync.aligned.m16n8k16.row.col.f32.bf16.bf16.f32 "
        "{%0,%1,%2,%3}, {%4,%5,%6,%7}, {%8,%9}, {%0,%1,%2,%3};"
        : "+f"(d[0]), "+f"(d[1]), "+f"(d[2]), "+f"(d[3])
        : "r"(a[0]), "r"(a[1]), "r"(a[2]), "r"(a[3]), "r"(b0), "r"(b1));
}

__device__ __forceinline__ void cmul(float& xr, float& xi, float yr, float yi) {
    const float t = xr * yr - xi * yi;
    xi = xr * yi + xi * yr;
    xr = t;
}

// hi/lo bf16 split store: hi at base+off, lo at base+off+plane
__device__ __forceinline__ void split_store(char* base, u32 off, int plane,
                                            float x, float y) {
    __nv_bfloat162 h = __float22bfloat162_rn(make_float2(x, y));
    float xl = x - __bfloat162float(h.x);
    float yl = y - __bfloat162float(h.y);
    __nv_bfloat162 l = __float22bfloat162_rn(make_float2(xl, yl));
    *reinterpret_cast<__nv_bfloat162*>(base + off)         = h;
    *reinterpret_cast<__nv_bfloat162*>(base + off + plane) = l;
}

__global__ __launch_bounds__(512, 3)
void s4d_kernel(const float* __restrict__ log_dt,
                const float* __restrict__ C,
                const float* __restrict__ log_A_real,
                const float* __restrict__ A_imag,
                float* __restrict__ out)
{
    __shared__ __align__(128) __nv_bfloat16 sP[2][128 * 64];  // hi, lo  32 KB
    __shared__ __align__(128) __nv_bfloat16 sQ[2][ 32 * 64];  // hi, lo   8 KB

    const int h    = blockIdx.x;
    const int tid  = threadIdx.x;
    const int lane = tid & 31;
    const int wrp  = tid >> 5;   // 0..15

    // ================= Phase 1: build swizzled bf16 hi/lo tiles ============
    {
        const int n = tid & 31;          // mode (stores span all 32 banks)
        const int s = tid >> 5;          // slice 0..15

        const float dt = expf(log_dt[h]);
        const float Ar = -expf(log_A_real[h * 32 + n]);
        const float Ai = A_imag[h * 32 + n];
        const float dr = dt * Ar, di = dt * Ai;

        // --- only transcendentals for w: 1 expf + 1 sincosf ---
        float sn, cs;
        const float er = expf(dr);
        sincosf(di, &sn, &cs);
        const float wr = er * cs, wi = er * sn;

        // P0 = 2*C*(w-1)/A
        const float inv = 1.0f / (Ar * Ar + Ai * Ai);
        const float nr = wr - 1.0f, ni = wi;
        const float gr = (nr * Ar + ni * Ai) * inv;
        const float gi = (ni * Ar - nr * Ai) * inv;
        const float Cr = C[(h * 32 + n) * 2 + 0];
        const float Ci = C[(h * 32 + n) * 2 + 1];
        const float p0r = 2.0f * (Cr * gr - Ci * gi);
        const float p0i = 2.0f * (Cr * gi + Ci * gr);

        // powers of w by repeated squaring
        float w8r = wr, w8i = wi;
        cmul(w8r, w8i, w8r, w8i);                    // w^2
        cmul(w8r, w8i, w8r, w8i);                    // w^4
        cmul(w8r, w8i, w8r, w8i);                    // w^8
        float w16r = w8r,  w16i = w8i;  cmul(w16r, w16i, w16r, w16i);   // w^16
        float w32r = w16r, w32i = w16i; cmul(w32r, w32i, w32r, w32i);   // w^32
        float w64r = w32r, w64i = w32i; cmul(w64r, w64i, w64r, w64i);   // w^64
        float wCr  = w64r, wCi  = w64i; cmul(wCr,  wCi,  wCr,  wCi);    // w^128

        // x = w^{8s} by binary powering over bits of s (select-multiply)
        float xr = 1.0f, xi = 0.0f;
        {
            float fr, fi;
            fr = (s & 1) ? w8r  : 1.0f;  fi = (s & 1) ? w8i  : 0.0f;  cmul(xr, xi, fr, fi);
            fr = (s & 2) ? w16r : 1.0f;  fi = (s & 2) ? w16i : 0.0f;  cmul(xr, xi, fr, fi);
            fr = (s & 4) ? w32r : 1.0f;  fi = (s & 4) ? w32i : 0.0f;  cmul(xr, xi, fr, fi);
            fr = (s & 8) ? w64r : 1.0f;  fi = (s & 8) ? w64i : 0.0f;  cmul(xr, xi, fr, fi);
        }

        // Q start = wC^{2s} = (w^{8s})^32 by 5 squarings
        float qr = xr, qi = xi;
        cmul(qr, qi, qr, qi);
        cmul(qr, qi, qr, qi);
        cmul(qr, qi, qr, qi);
        cmul(qr, qi, qr, qi);
        cmul(qr, qi, qr, qi);

        const u32 kb   = 4u * (u32)n;
        const u32 colb = ((u32)(n >> 2) << 4) | (kb & 15u);

        // ---- PT rows m in [8s, 8s+8): p = P0 * w^{8s}, step by w ----
        {
            float pr = p0r, pi = p0i;
            cmul(pr, pi, xr, xi);

            char* Pc = (char*)sP;
            const u32 pbase = (u32)(8 * s) * 128u + colb;
            #pragma unroll
            for (int k = 0; k < 8; k++) {
                const u32 off = (pbase ^ (((u32)k) << 4)) + (u32)k * 128u;
                split_store(Pc, off, PPLANE, pr, pi);
                cmul(pr, pi, wr, wi);
            }
        }

        // ---- QT rows c in [2s, 2s+2): q, then q*wC ----
        {
            char* Qc = (char*)sQ;
            const u32 qbase = (u32)(2 * s) * 128u + colb;
            const u32 xq    = 2u * (u32)(s & 3);
            #pragma unroll
            for (int k = 0; k < 2; k++) {
                const u32 off = (qbase ^ ((xq + (u32)k) << 4)) + (u32)k * 128u;
                split_store(Qc, off, QPLANE, qr, -qi);
                cmul(qr, qi, wCr, wCi);
            }
        }
    }
    __syncthreads();

    // ================= Phase 2: ldmatrix + mma.sync ========================
    // 16 warps: c-half r0 = 16*(wrp&1), m j-pair jp = wrp>>1 (j = 2jp, 2jp+1)
    const int gid = lane >> 2;
    const int tig = lane & 3;
    const int r0  = 16 * (wrp & 1);
    const int jp  = wrp >> 1;

    u32 aaddr[4], baddr[4];
    {
        const u32 Qb = smem_u32(sQ);
        const u32 Pb = smem_u32(sP);
        // A: row = r0 + (lane&15), k-half = lane>>4
        {
            const u32 row = (u32)(r0 + (lane & 15));
            const u32 hh  = (u32)(lane >> 4);
            const u32 rt  = Qb + row * 128u;
            const u32 x   = row & 7u;
            #pragma unroll
            for (int kc = 0; kc < 4; kc++)
                aaddr[kc] = rt + ((((2u * kc + hh) ^ x)) << 4);
        }
        // B: row = 8*(2jp + (lane>>4)) + (lane&7); k-half = (lane>>3)&1
        {
            const u32 row = 8u * (u32)(2 * jp + (lane >> 4)) + (lane & 7u);
            const u32 hb  = (u32)((lane >> 3) & 1);
            const u32 rt  = Pb + row * 128u;
            const u32 x   = row & 7u;
            #pragma unroll
            for (int kc = 0; kc < 4; kc++)
                baddr[kc] = rt + ((((2u * kc + hb) ^ x)) << 4);
        }
    }

    float acc[2][4];
    #pragma unroll
    for (int j = 0; j < 2; j++)
        #pragma unroll
        for (int r = 0; r < 4; r++) acc[j][r] = 0.0f;

    #pragma unroll
    for (int kc = 0; kc < 4; kc++) {
        u32 ahi[4], alo[4], bh[4], bl[4];
        ldsm4(aaddr[kc],          ahi);
        ldsm4(aaddr[kc] + QPLANE, alo);
        ldsm4(baddr[kc],          bh);
        ldsm4(baddr[kc] + PPLANE, bl);

        #pragma unroll
        for (int jj = 0; jj < 2; jj++) {
            const int o = jj * 2;
            mma_bf16(acc[jj], ahi, bh[o], bh[o + 1]);   // hi*hi
            mma_bf16(acc[jj], ahi, bl[o], bl[o + 1]);   // hi*lo
            mma_bf16(acc[jj], alo, bh[o], bh[o + 1]);   // lo*hi
        }
    }

    // ---- store D fragments: c = r0+gid (+8), m = 8*(2jp+jj) + 2*tig ----
    float* o = out + (size_t)h * 4096;
    #pragma unroll
    for (int jj = 0; jj < 2; jj++) {
        const int m = 8 * (2 * jp + jj) + 2 * tig;
        const int c = r0 + gid;
        *reinterpret_cast<float2*>(o + c * 128 + m) =
            make_float2(acc[jj][0], acc[jj][1]);
        *reinterpret_cast<float2*>(o + (c + 8) * 128 + m) =
            make_float2(acc[jj][2], acc[jj][3]);
    }
}

extern "C" void kernel_launch(void* const* d_in, const int* in_sizes, int n_in,
                              void* d_out, int out_size)
{
    const float* log_dt     = (const float*)d_in[0];
    const float* C          = (const float*)d_in[1];
    const float* log_A_real = (const float*)d_in[2];
    const float* A_imag     = (const float*)d_in[3];
    float*       out        = (float*)d_out;

    const int H = in_sizes[0];   // 1024
    s4d_kernel<<<H, 512>>>(log_dt, C, log_A_real, A_imag, out);
}

// round 15
// speedup vs baseline: 3.2924x; 1.1376x over previous
#include <cuda_runtime.h>
#include <cuda_fp16.h>
#include <cstdint>

// S4D via mma.sync fp16 single-pass (fp32 accum), R15:
//  Spend accuracy headroom: bf16 3-pass (rel_err 9e-6) -> fp16 1-pass
//  (predicted ~3e-4, threshold 1e-3). Phase-1 split machinery deleted
//  (one cvt+STS per entry), phase-2 MMA count /3, LDSM /2, smem 41->21KB.
//
// Per h:  K[m + 128c] = sum_k QT[c,k] * PT[m,k]
//   PT[m,2n] = Re(2*Ck_n*w_n^m),  PT[m,2n+1] = Im(...)
//   QT[c,2n] = Re((w_n^128)^c),   QT[c,2n+1] = -Im(...)
// GEMM M=32(c) x N=128(m) x K=64, mma.m16n8k16.row.col.f32.f16.f16.f32.
// Tiles k-major, 128B rows (64 fp16), 16B-chunk swizzle: chunk ^= (row&7).

typedef uint32_t u32;

__device__ __forceinline__ u32 smem_u32(const void* p) {
    u32 a;
    asm("{ .reg .u64 t; cvta.to.shared.u64 t, %1; cvt.u32.u64 %0, t; }"
        : "=r"(a) : "l"(p));
    return a;
}

__device__ __forceinline__ void ldsm4(u32 addr, u32* r) {
    asm volatile("ldmatrix.sync.aligned.m8n8.x4.shared.b16 {%0,%1,%2,%3}, [%4];"
                 : "=r"(r[0]), "=r"(r[1]), "=r"(r[2]), "=r"(r[3]) : "r"(addr));
}

__device__ __forceinline__ void mma_f16(float* d, const u32* a, u32 b0, u32 b1) {
    asm volatile(
        "mma.sync.aligned.m16n8k16.row.col.f32.f16.f16.f32 "
        "{%0,%1,%2,%3}, {%4,%5,%6,%7}, {%8,%9}, {%0,%1,%2,%3};"
        : "+f"(d[0]), "+f"(d[1]), "+f"(d[2]), "+f"(d[3])
        : "r"(a[0]), "r"(a[1]), "r"(a[2]), "r"(a[3]), "r"(b0), "r"(b1));
}

__device__ __forceinline__ void cmul(float& xr, float& xi, float yr, float yi) {
    const float t = xr * yr - xi * yi;
    xi = xr * yi + xi * yr;
    xr = t;
}

__device__ __forceinline__ void st_h2(char* base, u32 off, float x, float y) {
    *reinterpret_cast<__half2*>(base + off) =
        __float22half2_rn(make_float2(x, y));
}

__global__ __launch_bounds__(512, 3)
void s4d_kernel(const float* __restrict__ log_dt,
                const float* __restrict__ C,
                const float* __restrict__ log_A_real,
                const float* __restrict__ A_imag,
                float* __restrict__ out)
{
    __shared__ __align__(128) __half sP[128 * 64];  // 16 KB
    __shared__ __align__(128) __half sQ[ 32 * 64];  //  4 KB

    const int h    = blockIdx.x;
    const int tid  = threadIdx.x;
    const int lane = tid & 31;
    const int wrp  = tid >> 5;   // 0..15

    // ================= Phase 1: build swizzled fp16 tiles ==================
    {
        const int n = tid & 31;          // mode (stores span all 32 banks)
        const int s = tid >> 5;          // slice 0..15

        const float dt = expf(log_dt[h]);
        const float Ar = -expf(log_A_real[h * 32 + n]);
        const float Ai = A_imag[h * 32 + n];
        const float dr = dt * Ar, di = dt * Ai;

        float sn, cs;
        const float er = expf(dr);
        sincosf(di, &sn, &cs);
        const float wr = er * cs, wi = er * sn;

        // P0 = 2*C*(w-1)/A
        const float inv = 1.0f / (Ar * Ar + Ai * Ai);
        const float nr = wr - 1.0f, ni = wi;
        const float gr = (nr * Ar + ni * Ai) * inv;
        const float gi = (ni * Ar - nr * Ai) * inv;
        const float Cr = C[(h * 32 + n) * 2 + 0];
        const float Ci = C[(h * 32 + n) * 2 + 1];
        const float p0r = 2.0f * (Cr * gr - Ci * gi);
        const float p0i = 2.0f * (Cr * gi + Ci * gr);

        // powers of w by repeated squaring
        float w8r = wr, w8i = wi;
        cmul(w8r, w8i, w8r, w8i);                    // w^2
        cmul(w8r, w8i, w8r, w8i);                    // w^4
        cmul(w8r, w8i, w8r, w8i);                    // w^8
        float w16r = w8r,  w16i = w8i;  cmul(w16r, w16i, w16r, w16i);   // w^16
        float w32r = w16r, w32i = w16i; cmul(w32r, w32i, w32r, w32i);   // w^32
        float w64r = w32r, w64i = w32i; cmul(w64r, w64i, w64r, w64i);   // w^64
        float wCr  = w64r, wCi  = w64i; cmul(wCr,  wCi,  wCr,  wCi);    // w^128

        // x = w^{8s} by binary powering over bits of s
        float xr = 1.0f, xi = 0.0f;
        {
            float fr, fi;
            fr = (s & 1) ? w8r  : 1.0f;  fi = (s & 1) ? w8i  : 0.0f;  cmul(xr, xi, fr, fi);
            fr = (s & 2) ? w16r : 1.0f;  fi = (s & 2) ? w16i : 0.0f;  cmul(xr, xi, fr, fi);
            fr = (s & 4) ? w32r : 1.0f;  fi = (s & 4) ? w32i : 0.0f;  cmul(xr, xi, fr, fi);
            fr = (s & 8) ? w64r : 1.0f;  fi = (s & 8) ? w64i : 0.0f;  cmul(xr, xi, fr, fi);
        }

        // Q start = wC^{2s} = (w^{8s})^32 by 5 squarings
        float qr = xr, qi = xi;
        cmul(qr, qi, qr, qi);
        cmul(qr, qi, qr, qi);
        cmul(qr, qi, qr, qi);
        cmul(qr, qi, qr, qi);
        cmul(qr, qi, qr, qi);

        const u32 kb   = 4u * (u32)n;
        const u32 colb = ((u32)(n >> 2) << 4) | (kb & 15u);

        // ---- PT rows m in [8s, 8s+8): p = P0 * w^{8s}, step by w ----
        {
            float pr = p0r, pi = p0i;
            cmul(pr, pi, xr, xi);

            char* Pc = (char*)sP;
            const u32 pbase = (u32)(8 * s) * 128u + colb;
            #pragma unroll
            for (int k = 0; k < 8; k++) {
                const u32 off = (pbase ^ (((u32)k) << 4)) + (u32)k * 128u;
                st_h2(Pc, off, pr, pi);
                cmul(pr, pi, wr, wi);
            }
        }

        // ---- QT rows c in [2s, 2s+2): q, then q*wC ----
        {
            char* Qc = (char*)sQ;
            const u32 qbase = (u32)(2 * s) * 128u + colb;
            const u32 xq    = 2u * (u32)(s & 3);
            #pragma unroll
            for (int k = 0; k < 2; k++) {
                const u32 off = (qbase ^ ((xq + (u32)k) << 4)) + (u32)k * 128u;
                st_h2(Qc, off, qr, -qi);
                cmul(qr, qi, wCr, wCi);
            }
        }
    }
    __syncthreads();

    // ================= Phase 2: ldmatrix + mma.sync (fp16) =================
    // 16 warps: c-half r0 = 16*(wrp&1), m j-pair jp = wrp>>1 (j = 2jp, 2jp+1)
    const int gid = lane >> 2;
    const int tig = lane & 3;
    const int r0  = 16 * (wrp & 1);
    const int jp  = wrp >> 1;

    u32 aaddr[4], baddr[4];
    {
        const u32 Qb = smem_u32(sQ);
        const u32 Pb = smem_u32(sP);
        // A: row = r0 + (lane&15), k-half = lane>>4
        {
            const u32 row = (u32)(r0 + (lane & 15));
            const u32 hh  = (u32)(lane >> 4);
            const u32 rt  = Qb + row * 128u;
            const u32 x   = row & 7u;
            #pragma unroll
            for (int kc = 0; kc < 4; kc++)
                aaddr[kc] = rt + ((((2u * kc + hh) ^ x)) << 4);
        }
        // B: row = 8*(2jp + (lane>>4)) + (lane&7); k-half = (lane>>3)&1
        {
            const u32 row = 8u * (u32)(2 * jp + (lane >> 4)) + (lane & 7u);
            const u32 hb  = (u32)((lane >> 3) & 1);
            const u32 rt  = Pb + row * 128u;
            const u32 x   = row & 7u;
            #pragma unroll
            for (int kc = 0; kc < 4; kc++)
                baddr[kc] = rt + ((((2u * kc + hb) ^ x)) << 4);
        }
    }

    float acc[2][4];
    #pragma unroll
    for (int j = 0; j < 2; j++)
        #pragma unroll
        for (int r = 0; r < 4; r++) acc[j][r] = 0.0f;

    #pragma unroll
    for (int kc = 0; kc < 4; kc++) {
        u32 a[4], b[4];
        ldsm4(aaddr[kc], a);
        ldsm4(baddr[kc], b);

        #pragma unroll
        for (int jj = 0; jj < 2; jj++) {
            const int o = jj * 2;
            mma_f16(acc[jj], a, b[o], b[o + 1]);
        }
    }

    // ---- store D fragments: c = r0+gid (+8), m = 8*(2jp+jj) + 2*tig ----
    float* o = out + (size_t)h * 4096;
    #pragma unroll
    for (int jj = 0; jj < 2; jj++) {
        const int m = 8 * (2 * jp + jj) + 2 * tig;
        const int c = r0 + gid;
        *reinterpret_cast<float2*>(o + c * 128 + m) =
            make_float2(acc[jj][0], acc[jj][1]);
        *reinterpret_cast<float2*>(o + (c + 8) * 128 + m) =
            make_float2(acc[jj][2], acc[jj][3]);
    }
}

extern "C" void kernel_launch(void* const* d_in, const int* in_sizes, int n_in,
                              void* d_out, int out_size)
{
    const float* log_dt     = (const float*)d_in[0];
    const float* C          = (const float*)d_in[1];
    const float* log_A_real = (const float*)d_in[2];
    const float* A_imag     = (const float*)d_in[3];
    float*       out        = (float*)d_out;

    const int H = in_sizes[0];   // 1024
    s4d_kernel<<<H, 512>>>(log_dt, C, log_A_real, A_imag, out);
}

// round 17
// speedup vs baseline: 3.9881x; 1.2113x over previous
#include <cuda_runtime.h>
#include <cuda_fp16.h>
#include <cstdint>

// S4D via mma.sync fp16 single-pass (fp32 accum), R16:
//  Fast-math transcendentals (__expf/__sincosf, MUFU-based, ~5 instr each)
//  + DIRECT evaluation of all slice starts (w, w^{8s}, w^128, w^{256s}) —
//  deletes R14's 16-deep squaring/select cmul chains AND libm slow paths.
//  At fp16 operand precision (5e-4) the fast-path error (~1e-6 rel, and
//  sincos reduction error bounded by decay coupling) is invisible.
//
// Per h:  K[m + 128c] = sum_k QT[c,k] * PT[m,k]
//   PT[m,2n] = Re(2*Ck_n*w_n^m),  PT[m,2n+1] = Im(...)
//   QT[c,2n] = Re((w_n^128)^c),   QT[c,2n+1] = -Im(...)
// GEMM M=32(c) x N=128(m) x K=64, mma.m16n8k16.row.col.f32.f16.f16.f32.
// Tiles k-major, 128B rows (64 fp16), 16B-chunk swizzle: chunk ^= (row&7).

typedef uint32_t u32;

__device__ __forceinline__ u32 smem_u32(const void* p) {
    u32 a;
    asm("{ .reg .u64 t; cvta.to.shared.u64 t, %1; cvt.u32.u64 %0, t; }"
        : "=r"(a) : "l"(p));
    return a;
}

__device__ __forceinline__ void ldsm4(u32 addr, u32* r) {
    asm volatile("ldmatrix.sync.aligned.m8n8.x4.shared.b16 {%0,%1,%2,%3}, [%4];"
                 : "=r"(r[0]), "=r"(r[1]), "=r"(r[2]), "=r"(r[3]) : "r"(addr));
}

__device__ __forceinline__ void mma_f16(float* d, const u32* a, u32 b0, u32 b1) {
    asm volatile(
        "mma.sync.aligned.m16n8k16.row.col.f32.f16.f16.f32 "
        "{%0,%1,%2,%3}, {%4,%5,%6,%7}, {%8,%9}, {%0,%1,%2,%3};"
        : "+f"(d[0]), "+f"(d[1]), "+f"(d[2]), "+f"(d[3])
        : "r"(a[0]), "r"(a[1]), "r"(a[2]), "r"(a[3]), "r"(b0), "r"(b1));
}

__device__ __forceinline__ void cmul(float& xr, float& xi, float yr, float yi) {
    const float t = xr * yr - xi * yi;
    xi = xr * yi + xi * yr;
    xr = t;
}

// exp(re + i*im) via fast-math MUFU paths
__device__ __forceinline__ void cexp_fast(float re, float im,
                                          float& zr, float& zi) {
    float sn, cs;
    const float er = __expf(re);
    __sincosf(im, &sn, &cs);
    zr = er * cs;
    zi = er * sn;
}

__device__ __forceinline__ void st_h2(char* base, u32 off, float x, float y) {
    *reinterpret_cast<__half2*>(base + off) =
        __float22half2_rn(make_float2(x, y));
}

__global__ __launch_bounds__(512, 3)
void s4d_kernel(const float* __restrict__ log_dt,
                const float* __restrict__ C,
                const float* __restrict__ log_A_real,
                const float* __restrict__ A_imag,
                float* __restrict__ out)
{
    __shared__ __align__(128) __half sP[128 * 64];  // 16 KB
    __shared__ __align__(128) __half sQ[ 32 * 64];  //  4 KB

    const int h    = blockIdx.x;
    const int tid  = threadIdx.x;
    const int lane = tid & 31;
    const int wrp  = tid >> 5;   // 0..15

    // ================= Phase 1: build swizzled fp16 tiles ==================
    {
        const int n = tid & 31;          // mode (stores span all 32 banks)
        const int s = tid >> 5;          // slice 0..15

        const float dt = __expf(log_dt[h]);
        const float Ar = -__expf(log_A_real[h * 32 + n]);
        const float Ai = A_imag[h * 32 + n];
        const float dr = dt * Ar, di = dt * Ai;

        // w = exp(dt*A)
        float wr, wi;
        cexp_fast(dr, di, wr, wi);

        // P0 = 2*C*(w-1)/A
        const float inv = __fdividef(1.0f, Ar * Ar + Ai * Ai);
        const float nr = wr - 1.0f, ni = wi;
        const float gr = (nr * Ar + ni * Ai) * inv;
        const float gi = (ni * Ar - nr * Ai) * inv;
        const float Cr = C[(h * 32 + n) * 2 + 0];
        const float Ci = C[(h * 32 + n) * 2 + 1];
        const float p0r = 2.0f * (Cr * gr - Ci * gi);
        const float p0i = 2.0f * (Cr * gi + Ci * gr);

        // direct slice starts (all MUFU, no chains)
        float xr, xi;          // w^{8s}
        cexp_fast(dr * (float)(8 * s), di * (float)(8 * s), xr, xi);
        float wCr, wCi;        // w^128
        cexp_fast(dr * 128.0f, di * 128.0f, wCr, wCi);
        float qr, qi;          // w^{256 s} = Q start at c = 2s
        cexp_fast(dr * (float)(256 * s), di * (float)(256 * s), qr, qi);

        const u32 kb   = 4u * (u32)n;
        const u32 colb = ((u32)(n >> 2) << 4) | (kb & 15u);

        // ---- PT rows m in [8s, 8s+8): p = P0 * w^{8s}, step by w ----
        {
            float pr = p0r, pi = p0i;
            cmul(pr, pi, xr, xi);

            char* Pc = (char*)sP;
            const u32 pbase = (u32)(8 * s) * 128u + colb;
            #pragma unroll
            for (int k = 0; k < 8; k++) {
                const u32 off = (pbase ^ (((u32)k) << 4)) + (u32)k * 128u;
                st_h2(Pc, off, pr, pi);
                cmul(pr, pi, wr, wi);
            }
        }

        // ---- QT rows c in [2s, 2s+2): q, then q*wC ----
        {
            char* Qc = (char*)sQ;
            const u32 qbase = (u32)(2 * s) * 128u + colb;
            const u32 xq    = 2u * (u32)(s & 3);
            #pragma unroll
            for (int k = 0; k < 2; k++) {
                const u32 off = (qbase ^ ((xq + (u32)k) << 4)) + (u32)k * 128u;
                st_h2(Qc, off, qr, -qi);
                cmul(qr, qi, wCr, wCi);
            }
        }
    }
    __syncthreads();

    // ================= Phase 2: ldmatrix + mma.sync (fp16) =================
    // 16 warps: c-half r0 = 16*(wrp&1), m j-pair jp = wrp>>1 (j = 2jp, 2jp+1)
    const int gid = lane >> 2;
    const int tig = lane & 3;
    const int r0  = 16 * (wrp & 1);
    const int jp  = wrp >> 1;

    u32 aaddr[4], baddr[4];
    {
        const u32 Qb = smem_u32(sQ);
        const u32 Pb = smem_u32(sP);
        // A: row = r0 + (lane&15), k-half = lane>>4
        {
            const u32 row = (u32)(r0 + (lane & 15));
            const u32 hh  = (u32)(lane >> 4);
            const u32 rt  = Qb + row * 128u;
            const u32 x   = row & 7u;
            #pragma unroll
            for (int kc = 0; kc < 4; kc++)
                aaddr[kc] = rt + ((((2u * kc + hh) ^ x)) << 4);
        }
        // B: row = 8*(2jp + (lane>>4)) + (lane&7); k-half = (lane>>3)&1
        {
            const u32 row = 8u * (u32)(2 * jp + (lane >> 4)) + (lane & 7u);
            const u32 hb  = (u32)((lane >> 3) & 1);
            const u32 rt  = Pb + row * 128u;
            const u32 x   = row & 7u;
            #pragma unroll
            for (int kc = 0; kc < 4; kc++)
                baddr[kc] = rt + ((((2u * kc + hb) ^ x)) << 4);
        }
    }

    float acc[2][4];
    #pragma unroll
    for (int j = 0; j < 2; j++)
        #pragma unroll
        for (int r = 0; r < 4; r++) acc[j][r] = 0.0f;

    #pragma unroll
    for (int kc = 0; kc < 4; kc++) {
        u32 a[4], b[4];
        ldsm4(aaddr[kc], a);
        ldsm4(baddr[kc], b);

        #pragma unroll
        for (int jj = 0; jj < 2; jj++) {
            const int o = jj * 2;
            mma_f16(acc[jj], a, b[o], b[o + 1]);
        }
    }

    // ---- store D fragments: c = r0+gid (+8), m = 8*(2jp+jj) + 2*tig ----
    float* o = out + (size_t)h * 4096;
    #pragma unroll
    for (int jj = 0; jj < 2; jj++) {
        const int m = 8 * (2 * jp + jj) + 2 * tig;
        const int c = r0 + gid;
        *reinterpret_cast<float2*>(o + c * 128 + m) =
            make_float2(acc[jj][0], acc[jj][1]);
        *reinterpret_cast<float2*>(o + (c + 8) * 128 + m) =
            make_float2(acc[jj][2], acc[jj][3]);
    }
}

extern "C" void kernel_launch(void* const* d_in, const int* in_sizes, int n_in,
                              void* d_out, int out_size)
{
    const float* log_dt     = (const float*)d_in[0];
    const float* C          = (const float*)d_in[1];
    const float* log_A_real = (const float*)d_in[2];
    const float* A_imag     = (const float*)d_in[3];
    float*       out        = (float*)d_out;

    const int H = in_sizes[0];   // 1024
    s4d_kernel<<<H, 512>>>(log_dt, C, log_A_real, A_imag, out);
}